// round 4
// baseline (speedup 1.0000x reference)
#include <cuda_runtime.h>
#include <math.h>

#define NN 200000
#define NE 1600000
#define NB 1000
#define H  128

// ------------------------- device scratch (no allocs allowed) ----------------
__device__ float  g_xw [(size_t)NN * H];   // xW_gcn, later reused for h2
__device__ float  g_agg[(size_t)NN * H];   // GCN aggregate -> h0 (in place)
__device__ float  g_h1 [(size_t)NN * H];   // h1
__device__ float  g_deg[NN];               // degree -> dinv (in place)
__device__ double g_stats[6 * H];          // sum0,sq0,sum1,sq1,sum2,sq2
__device__ float  g_W1f[H * H];            // BN0-folded W1
__device__ float  g_b1f[H];
__device__ float  g_W3a[H], g_W3b[H];
__device__ float  g_c;
__device__ float  g_gsum[NB], g_gcnt[NB];
__device__ int    g_is64;

// ------------------------- index dtype detection -----------------------------
// JAX without x64 silently stores "int64" arrays as int32. If the buffer is
// truly int64, every value is a valid node id < NN. If it is int32 read as
// int64, values combine two random ids -> almost surely >= 2^32.
__global__ void k_detect(const long long* __restrict__ ei) {
    if (threadIdx.x == 0) {
        int ok = 1;
        for (int i = 0; i < 128; i++) {
            long long v = ei[i];
            if (v < 0 || v >= NN) ok = 0;
        }
        g_is64 = ok;
    }
}

// ------------------------- per-launch zero/init ------------------------------
__global__ void k_init() {
    int i = blockIdx.x * blockDim.x + threadIdx.x;
    if (i < 6 * H) g_stats[i] = 0.0;
    if (i < NB) { g_gsum[i] = 0.f; g_gcnt[i] = 0.f; }
}

__global__ void k_deginit() {
    int i = blockIdx.x * blockDim.x + threadIdx.x;
    if (i < NN) g_deg[i] = 1.0f;               // self loop
}

__global__ void k_edgedeg(const long long* __restrict__ e64,
                          const int* __restrict__ e32) {
    int is64 = g_is64;
    for (int e = blockIdx.x * blockDim.x + threadIdx.x; e < NE;
         e += gridDim.x * blockDim.x) {
        int d = is64 ? (int)e64[NE + e] : e32[NE + e];
        atomicAdd(&g_deg[d], 1.0f);
    }
}

__global__ void k_dinv() {
    int i = blockIdx.x * blockDim.x + threadIdx.x;
    if (i < NN) g_deg[i] = rsqrtf(g_deg[i]);   // now dinv
}

// ------------------------- fp32 SGEMM: C[N,128] = A[N,K] @ W[K,128] ----------
// BM=64, BN=128, BK=32, 256 threads, thread tile 8x4.
// EPI 0: C=g_xw and g_agg = C * dinv^2 (self-loop init).     (xw gemm, K=64)
// EPI 1: C=g_h1 = relu(C + bias), stats -> g_stats[2],[3].   (h1 gemm, K=128)
//        A/W/bias taken from device globals (g_agg/g_W1f/g_b1f) INSIDE device
//        code — passing __device__ symbols from host resolves to the host
//        shadow (and ATS on GB300 silently reads host zeros). Round-3 bug.
// EPI 2: C=g_xw = relu(C + bias), stats -> g_stats[4],[5].   (h2 gemm, K=32)
template<int K, int EPI>
__global__ void __launch_bounds__(256)
k_gemm(const float* __restrict__ Ain, const float* __restrict__ Win,
       const float* __restrict__ biasin) {
    const float* A    = (EPI == 1) ? (const float*)g_agg : Ain;
    const float* W    = (EPI == 1) ? (const float*)g_W1f : Win;
    const float* bias = (EPI == 1) ? (const float*)g_b1f : biasin;

    __shared__ float As[32][68];      // transposed A tile (padded)
    __shared__ float Ws[32][H];
    __shared__ float redS[8][H];
    __shared__ float redQ[8][H];

    const int tid = threadIdx.x;
    const int tx  = tid & 31;         // feature group: f0 = tx*4
    const int ty  = tid >> 5;         // node group:    m0 = ty*8
    const int f0  = tx * 4;
    const int m0  = ty * 8;
    const int bm  = blockIdx.x * 64;

    float acc[8][4];
#pragma unroll
    for (int i = 0; i < 8; i++)
#pragma unroll
        for (int j = 0; j < 4; j++) acc[i][j] = 0.f;

    for (int kb = 0; kb < K; kb += 32) {
        // A tile: 64 x 32, store transposed As[k][m]
#pragma unroll
        for (int i = 0; i < 2; i++) {
            int idx = tid + i * 256;             // 0..511 float4 slots
            int row = idx >> 3;
            int c4  = idx & 7;
            float4 v = *(const float4*)&A[(size_t)(bm + row) * K + kb + c4 * 4];
            As[c4 * 4 + 0][row] = v.x;
            As[c4 * 4 + 1][row] = v.y;
            As[c4 * 4 + 2][row] = v.z;
            As[c4 * 4 + 3][row] = v.w;
        }
        // W tile: 32 x 128
#pragma unroll
        for (int i = 0; i < 4; i++) {
            int idx = tid + i * 256;             // 0..1023 float4 slots
            int r  = idx >> 5;
            int c4 = idx & 31;
            *(float4*)&Ws[r][c4 * 4] =
                *(const float4*)&W[(size_t)(kb + r) * H + c4 * 4];
        }
        __syncthreads();
#pragma unroll
        for (int k = 0; k < 32; k++) {
            float4 a0 = *(float4*)&As[k][m0];
            float4 a1 = *(float4*)&As[k][m0 + 4];
            float4 w  = *(float4*)&Ws[k][f0];
            float am[8] = {a0.x, a0.y, a0.z, a0.w, a1.x, a1.y, a1.z, a1.w};
            float wm[4] = {w.x, w.y, w.z, w.w};
#pragma unroll
            for (int i = 0; i < 8; i++)
#pragma unroll
                for (int j = 0; j < 4; j++) acc[i][j] += am[i] * wm[j];
        }
        __syncthreads();
    }

    if (EPI == 0) {
#pragma unroll
        for (int i = 0; i < 8; i++) {
            int m = bm + m0 + i;
            float dv = g_deg[m];                 // dinv
            float d2 = dv * dv;
            float4 v  = make_float4(acc[i][0], acc[i][1], acc[i][2], acc[i][3]);
            float4 v2 = make_float4(v.x * d2, v.y * d2, v.z * d2, v.w * d2);
            *(float4*)&g_xw [(size_t)m * H + f0] = v;
            *(float4*)&g_agg[(size_t)m * H + f0] = v2;
        }
    } else {
        const float4 bb = *(const float4*)&bias[f0];
        float fs[4] = {0, 0, 0, 0}, fq[4] = {0, 0, 0, 0};
        float* dst = (EPI == 1) ? g_h1 : g_xw;
#pragma unroll
        for (int i = 0; i < 8; i++) {
            int m = bm + m0 + i;
            float v0 = fmaxf(acc[i][0] + bb.x, 0.f);
            float v1 = fmaxf(acc[i][1] + bb.y, 0.f);
            float v2 = fmaxf(acc[i][2] + bb.z, 0.f);
            float v3 = fmaxf(acc[i][3] + bb.w, 0.f);
            *(float4*)&dst[(size_t)m * H + f0] = make_float4(v0, v1, v2, v3);
            fs[0] += v0; fs[1] += v1; fs[2] += v2; fs[3] += v3;
            fq[0] += v0 * v0; fq[1] += v1 * v1; fq[2] += v2 * v2; fq[3] += v3 * v3;
        }
#pragma unroll
        for (int j = 0; j < 4; j++) { redS[ty][f0 + j] = fs[j]; redQ[ty][f0 + j] = fq[j]; }
        __syncthreads();
        if (tid < H) {
            float s = 0.f, q = 0.f;
#pragma unroll
            for (int t = 0; t < 8; t++) { s += redS[t][tid]; q += redQ[t][tid]; }
            const int soff = (EPI == 1) ? 2 : 4;
            atomicAdd(&g_stats[(size_t)soff * H + tid], (double)s);
            atomicAdd(&g_stats[(size_t)(soff + 1) * H + tid], (double)q);
        }
    }
}

// ------------------------- edge scatter (GCN aggregate) ----------------------
// One warp per edge: gather xw[src] (512B), scale by dinv[s]*dinv[d],
// red.global.add.v4.f32 into agg[dst].
__global__ void k_scatter(const long long* __restrict__ e64,
                          const int* __restrict__ e32) {
    const int is64   = g_is64;
    const int lane   = threadIdx.x & 31;
    const int warp   = (blockIdx.x * blockDim.x + threadIdx.x) >> 5;
    const int nwarps = (gridDim.x * blockDim.x) >> 5;
    for (int e = warp; e < NE; e += nwarps) {
        int s, d;
        if (is64) { s = (int)__ldg(&e64[e]); d = (int)__ldg(&e64[NE + e]); }
        else      { s = __ldg(&e32[e]);      d = __ldg(&e32[NE + e]); }
        float w = g_deg[s] * g_deg[d];
        float4 v = *(const float4*)&g_xw[(size_t)s * H + lane * 4];
        v.x *= w; v.y *= w; v.z *= w; v.w *= w;
        float* p = &g_agg[(size_t)d * H + lane * 4];
        asm volatile("red.global.add.v4.f32 [%0], {%1,%2,%3,%4};"
                     :: "l"(p), "f"(v.x), "f"(v.y), "f"(v.z), "f"(v.w)
                     : "memory");
    }
}

// ------------------------- h0 = relu(agg + b_gcn), BN0 stats -----------------
__global__ void k_h0(const float* __restrict__ bgcn) {
    const int f  = threadIdx.x & (H - 1);
    const float bv = bgcn[f];
    double s = 0.0, q = 0.0;
    const size_t total  = (size_t)NN * H;
    const size_t stride = (size_t)gridDim.x * blockDim.x;   // multiple of 128
    for (size_t i = (size_t)blockIdx.x * blockDim.x + threadIdx.x; i < total;
         i += stride) {
        float v = fmaxf(g_agg[i] + bv, 0.f);
        g_agg[i] = v;                   // g_agg now holds h0
        s += v; q += (double)v * v;
    }
    __shared__ double sS[256], sQ[256];
    sS[threadIdx.x] = s; sQ[threadIdx.x] = q;
    __syncthreads();
    if (threadIdx.x < H) {
        double ts = sS[threadIdx.x] + sS[threadIdx.x + H];
        double tq = sQ[threadIdx.x] + sQ[threadIdx.x + H];
        atomicAdd(&g_stats[0 * H + f], ts);
        atomicAdd(&g_stats[1 * H + f], tq);
    }
}

// ------------------------- fold BN0 into W1 ----------------------------------
__global__ void k_fold1(const float* __restrict__ g0, const float* __restrict__ be0,
                        const float* __restrict__ W1, const float* __restrict__ b1) {
    __shared__ float s0[H], t0[H];
    const int f = threadIdx.x;
    double mu  = g_stats[0 * H + f] / (double)NN;
    double var = g_stats[1 * H + f] / (double)NN - mu * mu;
    float  r   = (float)(1.0 / sqrt(var + 1e-5));
    float  sf  = g0[f] * r;
    float  tf  = be0[f] - (float)mu * sf;
    s0[f] = sf; t0[f] = tf;
    __syncthreads();
    float bacc = b1[f];
    for (int k = 0; k < H; k++) {
        float w = W1[k * H + f];
        g_W1f[k * H + f] = s0[k] * w;
        bacc += t0[k] * w;
    }
    g_b1f[f] = bacc;
}

// ------------------------- fold BN1/BN2 + W3 ---------------------------------
__global__ void k_fold3(const float* __restrict__ g1, const float* __restrict__ be1,
                        const float* __restrict__ g2, const float* __restrict__ be2,
                        const float* __restrict__ W3, const float* __restrict__ b3) {
    const int f = threadIdx.x;
    double mu1 = g_stats[2 * H + f] / (double)NN;
    double v1  = g_stats[3 * H + f] / (double)NN - mu1 * mu1;
    float  r1  = (float)(1.0 / sqrt(v1 + 1e-5));
    float  s1  = g1[f] * r1;
    float  t1  = be1[f] - (float)mu1 * s1;
    double mu2 = g_stats[4 * H + f] / (double)NN;
    double v2  = g_stats[5 * H + f] / (double)NN - mu2 * mu2;
    float  r2  = (float)(1.0 / sqrt(v2 + 1e-5));
    float  s2  = g2[f] * r2;
    float  t2  = be2[f] - (float)mu2 * s2;
    float w3a = W3[f], w3b = W3[H + f];
    g_W3a[f] = w3a * s1;
    g_W3b[f] = w3b * s2;
    __shared__ double red[H];
    red[f] = (double)(t1 * w3a) + (double)(t2 * w3b);
    __syncthreads();
    for (int o = 64; o > 0; o >>= 1) {
        if (f < o) red[f] += red[f + o];
        __syncthreads();
    }
    if (f == 0) g_c = (float)red[0] + b3[0];
}

// ------------------------- per-node scalar + segment sum ---------------------
__global__ void k_z(const long long* __restrict__ b64, const int* __restrict__ b32) {
    const int is64 = g_is64;
    const int lane = threadIdx.x & 31;
    const int n    = (blockIdx.x * blockDim.x + threadIdx.x) >> 5;
    if (n >= NN) return;
    float4 a  = *(const float4*)&g_h1[(size_t)n * H + lane * 4];
    float4 b  = *(const float4*)&g_xw[(size_t)n * H + lane * 4];   // h2
    float4 wa = *(const float4*)&g_W3a[lane * 4];
    float4 wb = *(const float4*)&g_W3b[lane * 4];
    float z = a.x * wa.x + a.y * wa.y + a.z * wa.z + a.w * wa.w +
              b.x * wb.x + b.y * wb.y + b.z * wb.z + b.w * wb.w;
#pragma unroll
    for (int o = 16; o > 0; o >>= 1) z += __shfl_xor_sync(0xffffffffu, z, o);
    if (lane == 0) {
        int g = is64 ? (int)b64[n] : b32[n];
        atomicAdd(&g_gsum[g], z);
        atomicAdd(&g_gcnt[g], 1.0f);
    }
}

__global__ void k_final(float* __restrict__ out, const float* __restrict__ b3) {
    int b = blockIdx.x * blockDim.x + threadIdx.x;
    if (b < NB) {
        float c = g_gcnt[b];
        out[b] = (c > 0.f) ? (g_gsum[b] / c + g_c) : b3[0];
    }
}

// ------------------------- launch ---------------------------------------------
extern "C" void kernel_launch(void* const* d_in, const int* in_sizes, int n_in,
                              void* d_out, int out_size) {
    const float* x      = (const float*)d_in[0];
    const float* action = (const float*)d_in[1];
    const float* W_gcn  = (const float*)d_in[2];
    const float* b_gcn  = (const float*)d_in[3];
    const float* g0     = (const float*)d_in[4];
    const float* be0    = (const float*)d_in[5];
    const float* W1     = (const float*)d_in[6];
    const float* b1     = (const float*)d_in[7];
    const float* g1     = (const float*)d_in[8];
    const float* be1    = (const float*)d_in[9];
    const float* W2     = (const float*)d_in[10];
    const float* b2     = (const float*)d_in[11];
    const float* g2     = (const float*)d_in[12];
    const float* be2    = (const float*)d_in[13];
    const float* W3     = (const float*)d_in[14];
    const float* b3     = (const float*)d_in[15];
    const long long* e64 = (const long long*)d_in[16];
    const int*       e32 = (const int*)d_in[16];
    const long long* bt64 = (const long long*)d_in[17];
    const int*       bt32 = (const int*)d_in[17];
    float* out = (float*)d_out;

    k_detect<<<1, 32>>>(e64);
    k_init<<<4, 256>>>();
    k_deginit<<<(NN + 255) / 256, 256>>>();
    k_edgedeg<<<1024, 256>>>(e64, e32);
    k_dinv<<<(NN + 255) / 256, 256>>>();
    k_gemm<64, 0><<<NN / 64, 256>>>(x, W_gcn, b_gcn);          // xw + self loop
    k_scatter<<<4096, 256>>>(e64, e32);
    k_h0<<<2048, 256>>>(b_gcn);
    k_fold1<<<1, H>>>(g0, be0, W1, b1);
    k_gemm<128, 1><<<NN / 64, 256>>>(nullptr, nullptr, nullptr); // h1 (globals)
    k_gemm<32, 2><<<NN / 64, 256>>>(action, W2, b2);             // h2 -> g_xw
    k_fold3<<<1, H>>>(g1, be1, g2, be2, W3, b3);
    k_z<<<NN / 8, 256>>>(bt64, bt32);
    k_final<<<4, 256>>>(out, b3);
}